// round 11
// baseline (speedup 1.0000x reference)
#include <cuda_runtime.h>
#include <cuda_bf16.h>
#include <math.h>
#include <cstdint>

#define NB   4096
#define MESH 778
#define NJ   16
#define NV   (MESH*3)        // 2334
#define KSEG 145             // real K: 135 pw + 10 beta
#define KBIG 448             // 3*145 = 435, padded to 448 (7 x 64)
#define NPAD 2432            // 19 * 128
#define KCH  64
#define NCHUNK (KBIG/KCH)    // 7
#define NBB  ((NPAD*56 + 255)/256)
#define NWB  ((NJ*MESH + 255)/256)   // weight-transpose blocks

#define OUT_J_OFF  (NB*MESH*3)
#define OUT_2D_OFF (NB*MESH*3 + NB*21*3)

// ---------------- device scratch ----------------
__device__ __align__(128) __nv_bfloat16 g_A2[(size_t)NB*KBIG];
__device__ __align__(128) __nv_bfloat16 g_B2[(size_t)NPAD*KBIG];
__device__ float g_vp  [(size_t)NB*NPAD];
__device__ float g_M   [NB*NJ*12];     // rotation-folded A matrices
__device__ float g_Jg  [NB*NJ*3];      // rotated global joint positions
__device__ float g_tips[NB*15];        // rotated fingertip vertices
__device__ float g_JS  [NJ*3*11];
__device__ __align__(16) float g_wT[NJ*800];  // transposed weights [j][m]

__constant__ int c_src21[21] = {0,1,2,3,16, 4,5,6,17, 7,8,9,18, 10,11,12,19, 13,14,15,20};

// ---------------- asm helpers ----------------
__device__ __forceinline__ uint32_t smem_u32(const void* p) {
    uint32_t a;
    asm("{ .reg .u64 t; cvta.to.shared.u64 t, %1; cvt.u32.u64 %0, t; }" : "=r"(a) : "l"(p));
    return a;
}
#define CP_ASYNC16(dst, src) \
    asm volatile("cp.async.cg.shared.global [%0], [%1], 16;" :: "r"(dst), "l"(src))
#define CP_COMMIT() asm volatile("cp.async.commit_group;" ::: "memory")
#define CP_WAIT(n)  asm volatile("cp.async.wait_group %0;" :: "n"(n) : "memory")

#define LDSM_X4(r, a) \
    asm volatile("ldmatrix.sync.aligned.m8n8.x4.shared.b16 {%0,%1,%2,%3}, [%4];" \
        : "=r"((r)[0]),"=r"((r)[1]),"=r"((r)[2]),"=r"((r)[3]) : "r"(a))

#define MMA16816(d, a, b0v, b1v) \
    asm volatile("mma.sync.aligned.m16n8k16.row.col.f32.bf16.bf16.f32 " \
        "{%0,%1,%2,%3}, {%4,%5,%6,%7}, {%8,%9}, {%0,%1,%2,%3};" \
        : "+f"((d)[0]),"+f"((d)[1]),"+f"((d)[2]),"+f"((d)[3]) \
        : "r"((a)[0]),"r"((a)[1]),"r"((a)[2]),"r"((a)[3]), "r"(b0v),"r"(b1v))

typedef unsigned long long ull;
#define FFMA2(d, a, b, c) \
    asm("fma.rn.f32x2 %0, %1, %2, %3;" : "=l"(d) : "l"(a), "l"(b), "l"(c))
__device__ __forceinline__ ull pk2(float a, float b) {
    ull r; asm("mov.b64 %0, {%1,%2};" : "=l"(r) : "f"(a), "f"(b)); return r;
}
__device__ __forceinline__ void upk2(ull v, float& a, float& b) {
    asm("mov.b64 {%0,%1}, %2;" : "=f"(a), "=f"(b) : "l"(v));
}

// ---------------- bf16 hi/lo split ----------------
__device__ __forceinline__ unsigned short bf_hi(float f) {
    __nv_bfloat16 h = __float2bfloat16(f);
    return reinterpret_cast<unsigned short&>(h);
}
__device__ __forceinline__ unsigned short bf_lo(float f) {
    __nv_bfloat16 h = __float2bfloat16(f);
    float r = f - __bfloat162float(h);
    __nv_bfloat16 l = __float2bfloat16(r);
    return reinterpret_cast<unsigned short&>(l);
}

// ---------------- Rodrigues ----------------
__device__ __forceinline__ void rodrigues9(float x, float y, float z, float* R) {
    float t2 = x*x + y*y + z*z;
    float th = sqrtf(t2);
    bool small = th < 1e-30f;
    float ts = small ? 1.f : th;
    float nx = x/ts, ny = y/ts, nz = z/ts;
    float sn = sinf(th), cs = cosf(th), oc = 1.f - cs;
    R[0] = cs + oc*nx*nx;      R[1] = oc*nx*ny - sn*nz;  R[2] = oc*nx*nz + sn*ny;
    R[3] = oc*nx*ny + sn*nz;   R[4] = cs + oc*ny*ny;     R[5] = oc*ny*nz - sn*nx;
    R[6] = oc*nx*nz - sn*ny;   R[7] = oc*ny*nz + sn*nx;  R[8] = cs + oc*nz*nz;
    if (small) {
        float a  = 1.f  - t2/6.f;
        float bq = 0.5f - t2/24.f;
        R[0] = 1.f + bq*(x*x - t2);  R[1] = bq*x*y - a*z;        R[2] = bq*x*z + a*y;
        R[3] = bq*x*y + a*z;         R[4] = 1.f + bq*(y*y - t2); R[5] = bq*y*z - a*x;
        R[6] = bq*x*z - a*y;         R[7] = bq*y*z + a*x;        R[8] = 1.f + bq*(z*z - t2);
    }
}

// ---------------- fused prep: B' pack + JS fold + weight transpose ------------
__global__ void __launch_bounds__(256) k_prep(const float* __restrict__ pd,
                                              const float* __restrict__ sd,
                                              const float* __restrict__ Jreg,
                                              const float* __restrict__ mu,
                                              const float* __restrict__ w) {
    if (blockIdx.x < NBB) {
        int t = blockIdx.x*256 + threadIdx.x;
        if (t >= NPAD*56) return;
        int n = t / 56, q = t % 56;
        int kbase = q*8;
        union { unsigned short s[8]; uint4 v; } pk;
        #pragma unroll
        for (int i = 0; i < 8; i++) {
            int k = kbase + i;
            int seg = (k < KSEG) ? 0 : ((k < 2*KSEG) ? 1 : ((k < 3*KSEG) ? 2 : 3));
            int kr  = k - seg*KSEG;
            float f = 0.f;
            if (seg < 3 && n < NV) {
                f = (kr < 135) ? pd[n*135 + kr] : sd[n*10 + (kr - 135)];
            }
            pk.s[i] = (seg == 2) ? bf_lo(f) : bf_hi(f);
        }
        *(uint4*)(g_B2 + (size_t)n*KBIG + kbase) = pk.v;
    } else if (blockIdx.x < NBB + 66) {
        int wi = (blockIdx.x - NBB)*8 + (threadIdx.x >> 5);
        int lane = threadIdx.x & 31;
        if (wi >= NJ*33) return;
        int j = wi / 33, rem = wi % 33, c = rem / 11, k = rem % 11;
        float s = 0.f;
        for (int m = lane; m < MESH; m += 32) {
            float jr = Jreg[j*MESH + m];
            float x  = (k < 10) ? sd[(m*3+c)*10 + k] : mu[m*3+c];
            s = fmaf(jr, x, s);
        }
        #pragma unroll
        for (int off = 16; off; off >>= 1) s += __shfl_xor_sync(0xffffffffu, s, off);
        if (lane == 0) g_JS[j*33 + c*11 + k] = s;
    } else {
        int idx = (blockIdx.x - NBB - 66)*256 + threadIdx.x;
        if (idx >= NJ*MESH) return;
        int j = idx / MESH, m = idx % MESH;
        g_wT[j*800 + m] = w[m*16 + j];
    }
}

// ---------------- per-batch kinematics + A' pack (fused, rot-folded) ----------
__global__ void __launch_bounds__(256) k_batch(const float* __restrict__ theta,
                                               const float* __restrict__ beta,
                                               const float* __restrict__ hc,
                                               const float* __restrict__ hm) {
    __shared__ float su[8][160];
    int warp = threadIdx.x >> 5;
    int lane = threadIdx.x & 31;
    int b = blockIdx.x*8 + warp;
    if (b >= NB) return;

    float px, py, pz;
    if (lane == 0) { px = 3.14159265358979323846f; py = 0.f; pz = 0.f; }
    else if (lane <= 15) {
        int i3 = (lane-1)*3;
        float s0 = hm[i3], s1 = hm[i3+1], s2 = hm[i3+2];
        const float* th = theta + b*48 + 3;
        #pragma unroll 5
        for (int k = 0; k < 45; k++) {
            float t = th[k];
            const float* h = hc + k*45 + i3;
            s0 = fmaf(t, h[0], s0);
            s1 = fmaf(t, h[1], s1);
            s2 = fmaf(t, h[2], s2);
        }
        px = s0; py = s1; pz = s2;
    } else {
        px = theta[b*48]; py = theta[b*48+1]; pz = theta[b*48+2];
    }

    float R[9];
    rodrigues9(px, py, pz, R);

    if (lane >= 1 && lane <= 15) {
        float* u = su[warp] + (lane-1)*9;
        #pragma unroll
        for (int e = 0; e < 9; e++)
            u[e] = R[e] - ((e==0||e==4||e==8) ? 1.f : 0.f);
    }
    if (lane < 10) su[warp][135 + lane] = beta[b*10 + lane];
    __syncwarp();

    // pack A' row
    {
        const float* u = su[warp];
        #pragma unroll
        for (int q = lane; q < 56; q += 32) {
            int kbase = q*8;
            union { unsigned short s[8]; uint4 v; } pk;
            #pragma unroll
            for (int i = 0; i < 8; i++) {
                int k = kbase + i;
                int seg = (k < KSEG) ? 0 : ((k < 2*KSEG) ? 1 : ((k < 3*KSEG) ? 2 : 3));
                int kr  = k - seg*KSEG;
                float f = (seg < 3) ? u[kr] : 0.f;
                pk.s[i] = (seg == 1) ? bf_lo(f) : bf_hi(f);
            }
            *(uint4*)(g_A2 + (size_t)b*KBIG + kbase) = pk.v;
        }
    }

    int jj = (lane < 16) ? lane : 15;
    float Jx, Jy, Jz;
    {
        const float* JS = g_JS + jj*33;
        float a0 = JS[10], a1 = JS[21], a2 = JS[32];
        #pragma unroll
        for (int k = 0; k < 10; k++) {
            float bb = beta[b*10+k];
            a0 = fmaf(bb, JS[k],    a0);
            a1 = fmaf(bb, JS[11+k], a1);
            a2 = fmaf(bb, JS[22+k], a2);
        }
        Jx = a0; Jy = a1; Jz = a2;
    }

    int pj = (jj == 0) ? 0 : ((jj % 3 == 1) ? 0 : jj - 1);
    float Jpx = __shfl_sync(0xffffffffu, Jx, pj);
    float Jpy = __shfl_sync(0xffffffffu, Jy, pj);
    float Jpz = __shfl_sync(0xffffffffu, Jz, pj);
    float tx = (jj == 0) ? Jx : Jx - Jpx;
    float ty = (jj == 0) ? Jy : Jy - Jpy;
    float tz = (jj == 0) ? Jz : Jz - Jpz;

    float G[12] = {R[0],R[1],R[2],tx, R[3],R[4],R[5],ty, R[6],R[7],R[8],tz};
    int lvl = (jj == 0) ? 0 : ((jj-1)%3 + 1);
    #pragma unroll
    for (int r = 1; r <= 3; r++) {
        float Gp[12];
        #pragma unroll
        for (int e = 0; e < 12; e++) Gp[e] = __shfl_sync(0xffffffffu, G[e], pj);
        if (lvl == r) {
            float N[12];
            #pragma unroll
            for (int rr = 0; rr < 3; rr++) {
                #pragma unroll
                for (int cc = 0; cc < 4; cc++) {
                    float s = Gp[rr*4+0]*G[0*4+cc] + Gp[rr*4+1]*G[1*4+cc] + Gp[rr*4+2]*G[2*4+cc];
                    if (cc == 3) s += Gp[rr*4+3];
                    N[rr*4+cc] = s;
                }
            }
            #pragma unroll
            for (int e = 0; e < 12; e++) G[e] = N[e];
        }
    }

    // broadcast the global rotation (lane 16's R)
    float Rg[9];
    #pragma unroll
    for (int e = 0; e < 9; e++) Rg[e] = __shfl_sync(0xffffffffu, R[e], 16);

    if (lane < 16) {
        // rotated global joint position
        g_Jg[b*48 + jj*3 + 0] = Rg[0]*G[3] + Rg[1]*G[7] + Rg[2]*G[11];
        g_Jg[b*48 + jj*3 + 1] = Rg[3]*G[3] + Rg[4]*G[7] + Rg[5]*G[11];
        g_Jg[b*48 + jj*3 + 2] = Rg[6]*G[3] + Rg[7]*G[7] + Rg[8]*G[11];
        // corrected A, then fold rotation: A' = Rg * A
        float M[12];
        #pragma unroll
        for (int rr = 0; rr < 3; rr++) {
            float cr = G[rr*4+0]*Jx + G[rr*4+1]*Jy + G[rr*4+2]*Jz;
            M[rr*4+0] = G[rr*4+0];
            M[rr*4+1] = G[rr*4+1];
            M[rr*4+2] = G[rr*4+2];
            M[rr*4+3] = G[rr*4+3] - cr;
        }
        float* Mo = g_M + b*192 + jj*12;
        #pragma unroll
        for (int rr = 0; rr < 3; rr++)
            #pragma unroll
            for (int cc = 0; cc < 4; cc++)
                Mo[rr*4+cc] = Rg[rr*3+0]*M[0*4+cc] + Rg[rr*3+1]*M[1*4+cc] + Rg[rr*3+2]*M[2*4+cc];
    }
}

// ---------------- mma.sync GEMM (3-stage pipeline, 2 CTA/SM) ------------------
#define STAGE_BYTES 32768

__global__ void __launch_bounds__(256, 2) k_mma2(const float* __restrict__ mu) {
    extern __shared__ char smem[];
    uint32_t sb = smem_u32(smem);
    int tid = threadIdx.x, wid = tid >> 5, lane = tid & 31;
    int bx = blockIdx.x, by = blockIdx.y;

    const __nv_bfloat16* Ag = g_A2 + (size_t)by*128*KBIG;
    const __nv_bfloat16* Bg = g_B2 + (size_t)bx*128*KBIG;

    int m0 = (wid >> 1)*32;
    int n0 = (wid & 1)*64;

    float acc[2][8][4];
    #pragma unroll
    for (int i = 0; i < 2; i++)
        #pragma unroll
        for (int j = 0; j < 8; j++)
            #pragma unroll
            for (int e = 0; e < 4; e++) acc[i][j][e] = 0.f;

    auto load_stage = [&](int kc, int s) {
        uint32_t dA = sb + s*STAGE_BYTES;
        uint32_t dB = dA + 16384;
        #pragma unroll
        for (int i = 0; i < 4; i++) {
            int idx = i*256 + tid;
            int row = idx >> 3, ch = idx & 7;
            int sw  = ch ^ (row & 7);
            CP_ASYNC16(dA + row*128 + sw*16,
                       (const char*)__cvta_generic_to_global(Ag + (size_t)row*KBIG + kc*KCH + ch*8));
            CP_ASYNC16(dB + row*128 + sw*16,
                       (const char*)__cvta_generic_to_global(Bg + (size_t)row*KBIG + kc*KCH + ch*8));
        }
        CP_COMMIT();
    };

    load_stage(0, 0);
    load_stage(1, 1);
    load_stage(2, 2);

    #pragma unroll
    for (int kc = 0; kc < NCHUNK; kc++) {
        if (kc <= NCHUNK - 3)      { CP_WAIT(2); }
        else if (kc == NCHUNK - 2) { CP_WAIT(1); }
        else                       { CP_WAIT(0); }
        __syncthreads();
        uint32_t A0 = sb + (kc % 3)*STAGE_BYTES;
        uint32_t B0 = A0 + 16384;
        #pragma unroll
        for (int kk = 0; kk < 4; kk++) {
            uint32_t a[2][4];
            #pragma unroll
            for (int mf = 0; mf < 2; mf++) {
                int row = m0 + mf*16 + (lane & 15);
                int ch  = kk*2 + (lane >> 4);
                LDSM_X4(a[mf], A0 + row*128 + (ch ^ (row & 7))*16);
            }
            uint32_t bfr[4][4];
            #pragma unroll
            for (int nf2 = 0; nf2 < 4; nf2++) {
                int rn = n0 + nf2*16 + ((lane >> 4) & 1)*8 + (lane & 7);
                int ch = kk*2 + ((lane >> 3) & 1);
                LDSM_X4(bfr[nf2], B0 + rn*128 + (ch ^ (rn & 7))*16);
            }
            #pragma unroll
            for (int mf = 0; mf < 2; mf++)
                #pragma unroll
                for (int nf2 = 0; nf2 < 4; nf2++) {
                    MMA16816(acc[mf][2*nf2],   a[mf], bfr[nf2][0], bfr[nf2][1]);
                    MMA16816(acc[mf][2*nf2+1], a[mf], bfr[nf2][2], bfr[nf2][3]);
                }
        }
        __syncthreads();
        if (kc + 3 < NCHUNK) load_stage(kc + 3, kc % 3);
    }

    int qr = lane >> 2, qc = (lane & 3)*2;
    #pragma unroll
    for (int mf = 0; mf < 2; mf++) {
        int r0 = by*128 + m0 + mf*16 + qr;
        #pragma unroll
        for (int nf = 0; nf < 8; nf++) {
            int c = bx*128 + n0 + nf*8 + qc;
            float mv0 = (c   < NV) ? mu[c]   : 0.f;
            float mv1 = (c+1 < NV) ? mu[c+1] : 0.f;
            float2 v0 = make_float2(acc[mf][nf][0] + mv0, acc[mf][nf][1] + mv1);
            float2 v1 = make_float2(acc[mf][nf][2] + mv0, acc[mf][nf][3] + mv1);
            *(float2*)(g_vp + (size_t)r0*NPAD + c)       = v0;
            *(float2*)(g_vp + (size_t)(r0+8)*NPAD + c)   = v1;
        }
    }
}

// ---------------- skinning v5: vertex-pair SIMD, weights via L2 ---------------
// block 256 threads; slot0: vpair tx, slot1: vpair 256+tx (tx<133); BG=8 batches.
#define BG 8
#define SKT 256

__device__ __forceinline__ void tip_info(int v, int& tip, int& th) {
    tip = -1; th = 0;
    if (v == 166) { tip = 0; th = 1; }       // 333
    else if (v == 222) { tip = 1; th = 0; }  // 444
    else if (v == 277) { tip = 3; th = 1; }  // 555
    else if (v == 336) { tip = 2; th = 0; }  // 672
    else if (v == 372) { tip = 4; th = 1; }  // 745
}

__device__ __forceinline__ void load_pv(const float* p, ull* pv) {
    float2 q0 = *(const float2*)(p);
    float2 q1 = *(const float2*)(p + 2);
    float2 q2 = *(const float2*)(p + 4);
    pv[0] = pk2(q0.x, q1.y);
    pv[1] = pk2(q0.y, q2.x);
    pv[2] = pk2(q1.x, q2.y);
}

__device__ __forceinline__ void skin_j(const ull* A, ull w, const ull* pv, ull* ac) {
    ull r0 = A[3], r1 = A[7], r2 = A[11];
    FFMA2(r0, A[0],  pv[0], r0); FFMA2(r0, A[1], pv[1], r0); FFMA2(r0, A[2],  pv[2], r0);
    FFMA2(r1, A[4],  pv[0], r1); FFMA2(r1, A[5], pv[1], r1); FFMA2(r1, A[6],  pv[2], r1);
    FFMA2(r2, A[8],  pv[0], r2); FFMA2(r2, A[9], pv[1], r2); FFMA2(r2, A[10], pv[2], r2);
    FFMA2(ac[0], w, r0, ac[0]);
    FFMA2(ac[1], w, r1, ac[1]);
    FFMA2(ac[2], w, r2, ac[2]);
}

__device__ __forceinline__ void store_slot(float* out, int b, int v, const ull* ac,
                                           int tip, int th) {
    float xa, xb, ya, yb, za, zb;
    upk2(ac[0], xa, xb); upk2(ac[1], ya, yb); upk2(ac[2], za, zb);
    if (tip >= 0) {
        g_tips[b*15 + tip*3 + 0] = th ? xb : xa;
        g_tips[b*15 + tip*3 + 1] = th ? yb : ya;
        g_tips[b*15 + tip*3 + 2] = th ? zb : za;
    }
    float* o = out + (size_t)b*NV + 6*v;
    *(float2*)(o)     = make_float2(xa, ya);
    *(float2*)(o + 2) = make_float2(za, xb);
    *(float2*)(o + 4) = make_float2(yb, zb);
}

__global__ void __launch_bounds__(SKT) k_skin(float* __restrict__ out) {
    __shared__ ull sA[BG][192];
    int by = blockIdx.x;
    int tx = threadIdx.x;

    for (int i = tx; i < BG*192; i += SKT) {
        int bg = i / 192, e = i % 192;
        float a = g_M[(size_t)(by*BG + bg)*192 + e];
        sA[bg][e] = pk2(a, a);
    }
    __syncthreads();

    int v0 = tx;
    int v1 = 256 + tx;
    bool has1 = (tx < 133);
    int tip0, th0, tip1, th1;
    tip_info(v0, tip0, th0);
    tip_info(v1, tip1, th1);

    #pragma unroll 1
    for (int bg = 0; bg < BG; bg++) {
        int b = by*BG + bg;
        const float* vpr = g_vp + (size_t)b*NPAD;

        ull pv0[3], pv1[3];
        load_pv(vpr + 6*v0, pv0);
        if (has1) load_pv(vpr + 6*v1, pv1);

        ull ac0[3] = {0,0,0}, ac1[3] = {0,0,0};
        const ull* A = sA[bg];

        #pragma unroll
        for (int j = 0; j < 16; j++) {
            const ull* Aj = A + j*12;
            ull w0 = *(const ull*)(g_wT + j*800 + 2*v0);
            skin_j(Aj, w0, pv0, ac0);
            if (has1) {
                ull w1 = *(const ull*)(g_wT + j*800 + 2*v1);
                skin_j(Aj, w1, pv1, ac1);
            }
        }

        store_slot(out, b, v0, ac0, tip0, th0);
        if (has1) store_slot(out, b, v1, ac1, tip1, th1);
    }
}

// ---------------- joints (21): pure gather + 2D projection --------------------
__global__ void k_joints(const float* __restrict__ cam, float* __restrict__ out) {
    int idx = blockIdx.x*256 + threadIdx.x;
    if (idx >= NB*21) return;
    int b = idx / 21, s = idx % 21;
    int src = c_src21[s];
    float x, y, z;
    if (src < 16) {
        x = g_Jg[b*48 + src*3 + 0];
        y = g_Jg[b*48 + src*3 + 1];
        z = g_Jg[b*48 + src*3 + 2];
    } else {
        int t = src - 16;
        x = g_tips[b*15 + t*3 + 0];
        y = g_tips[b*15 + t*3 + 1];
        z = g_tips[b*15 + t*3 + 2];
    }
    out[OUT_J_OFF + idx*3 + 0] = x;
    out[OUT_J_OFF + idx*3 + 1] = y;
    out[OUT_J_OFF + idx*3 + 2] = z;
    float c0 = cam[b*3], c1 = cam[b*3+1], c2 = cam[b*3+2];
    out[OUT_2D_OFF + idx*2 + 0] = fmaf(c0, x, c1);
    out[OUT_2D_OFF + idx*2 + 1] = fmaf(c0, y, c2);
}

// ---------------- launch ----------------
extern "C" void kernel_launch(void* const* d_in, const int* in_sizes, int n_in,
                              void* d_out, int out_size) {
    const float* theta     = (const float*)d_in[0];
    const float* beta      = (const float*)d_in[1];
    const float* cam       = (const float*)d_in[2];
    const float* mesh_mu   = (const float*)d_in[3];
    const float* shapedirs = (const float*)d_in[4];
    const float* posedirs  = (const float*)d_in[5];
    const float* Jreg      = (const float*)d_in[6];
    const float* weights   = (const float*)d_in[7];
    const float* hc        = (const float*)d_in[8];
    const float* hm        = (const float*)d_in[9];
    float* out = (float*)d_out;

    cudaFuncSetAttribute(k_mma2, cudaFuncAttributeMaxDynamicSharedMemorySize, 3*STAGE_BYTES);

    k_prep<<<NBB + 66 + NWB, 256>>>(posedirs, shapedirs, Jreg, mesh_mu, weights);
    k_batch<<<NB/8, 256>>>(theta, beta, hc, hm);
    dim3 gm(NPAD/128, NB/128);
    k_mma2<<<gm, 256, 3*STAGE_BYTES>>>(mesh_mu);
    k_skin<<<NB/BG, SKT>>>(out);
    k_joints<<<(NB*21 + 255)/256, 256>>>(cam, out);
}

// round 13
// speedup vs baseline: 1.2503x; 1.2503x over previous
#include <cuda_runtime.h>
#include <cuda_bf16.h>
#include <math.h>
#include <cstdint>

#define NB   4096
#define MESH 778
#define NJ   16
#define NV   (MESH*3)        // 2334
#define KSEG 145             // real K: 135 pw + 10 beta
#define KBIG 448             // 3*145 = 435, padded to 448 (7 x 64)
#define NPAD 2432            // 19 * 128
#define KCH  64
#define NCHUNK (KBIG/KCH)    // 7
#define NBB  ((NPAD*56 + 255)/256)
#define NWB  ((NJ*800 + 255)/256)    // 50 blocks — covers the FULL padded g_wT

#define OUT_J_OFF  (NB*MESH*3)
#define OUT_2D_OFF (NB*MESH*3 + NB*21*3)

// ---------------- device scratch ----------------
__device__ __align__(128) __nv_bfloat16 g_A2[(size_t)NB*KBIG];
__device__ __align__(128) __nv_bfloat16 g_B2[(size_t)NPAD*KBIG];
__device__ float g_vp  [(size_t)NB*NPAD];
__device__ float g_M   [NB*NJ*12];     // rotation-folded A matrices
__device__ float g_Jg  [NB*NJ*3];      // rotated global joint positions
__device__ float g_tips[NB*15];        // rotated fingertip vertices
__device__ float g_JS  [NJ*3*11];
__device__ __align__(16) float g_wT[NJ*800];  // transposed weights [j][m], padded

__constant__ int c_src21[21] = {0,1,2,3,16, 4,5,6,17, 7,8,9,18, 10,11,12,19, 13,14,15,20};

// ---------------- asm helpers ----------------
__device__ __forceinline__ uint32_t smem_u32(const void* p) {
    uint32_t a;
    asm("{ .reg .u64 t; cvta.to.shared.u64 t, %1; cvt.u32.u64 %0, t; }" : "=r"(a) : "l"(p));
    return a;
}
#define CP_ASYNC16(dst, src) \
    asm volatile("cp.async.cg.shared.global [%0], [%1], 16;" :: "r"(dst), "l"(src))
#define CP_COMMIT() asm volatile("cp.async.commit_group;" ::: "memory")
#define CP_WAIT(n)  asm volatile("cp.async.wait_group %0;" :: "n"(n) : "memory")

#define LDSM_X4(r, a) \
    asm volatile("ldmatrix.sync.aligned.m8n8.x4.shared.b16 {%0,%1,%2,%3}, [%4];" \
        : "=r"((r)[0]),"=r"((r)[1]),"=r"((r)[2]),"=r"((r)[3]) : "r"(a))

#define MMA16816(d, a, b0v, b1v) \
    asm volatile("mma.sync.aligned.m16n8k16.row.col.f32.bf16.bf16.f32 " \
        "{%0,%1,%2,%3}, {%4,%5,%6,%7}, {%8,%9}, {%0,%1,%2,%3};" \
        : "+f"((d)[0]),"+f"((d)[1]),"+f"((d)[2]),"+f"((d)[3]) \
        : "r"((a)[0]),"r"((a)[1]),"r"((a)[2]),"r"((a)[3]), "r"(b0v),"r"(b1v))

typedef unsigned long long ull;
#define FFMA2(d, a, b, c) \
    asm("fma.rn.f32x2 %0, %1, %2, %3;" : "=l"(d) : "l"(a), "l"(b), "l"(c))
__device__ __forceinline__ ull pk2(float a, float b) {
    ull r; asm("mov.b64 %0, {%1,%2};" : "=l"(r) : "f"(a), "f"(b)); return r;
}
__device__ __forceinline__ void upk2(ull v, float& a, float& b) {
    asm("mov.b64 {%0,%1}, %2;" : "=f"(a), "=f"(b) : "l"(v));
}

// ---------------- bf16 hi/lo split ----------------
__device__ __forceinline__ unsigned short bf_hi(float f) {
    __nv_bfloat16 h = __float2bfloat16(f);
    return reinterpret_cast<unsigned short&>(h);
}
__device__ __forceinline__ unsigned short bf_lo(float f) {
    __nv_bfloat16 h = __float2bfloat16(f);
    float r = f - __bfloat162float(h);
    __nv_bfloat16 l = __float2bfloat16(r);
    return reinterpret_cast<unsigned short&>(l);
}

// ---------------- Rodrigues ----------------
__device__ __forceinline__ void rodrigues9(float x, float y, float z, float* R) {
    float t2 = x*x + y*y + z*z;
    float th = sqrtf(t2);
    bool small = th < 1e-30f;
    float ts = small ? 1.f : th;
    float nx = x/ts, ny = y/ts, nz = z/ts;
    float sn = sinf(th), cs = cosf(th), oc = 1.f - cs;
    R[0] = cs + oc*nx*nx;      R[1] = oc*nx*ny - sn*nz;  R[2] = oc*nx*nz + sn*ny;
    R[3] = oc*nx*ny + sn*nz;   R[4] = cs + oc*ny*ny;     R[5] = oc*ny*nz - sn*nx;
    R[6] = oc*nx*nz - sn*ny;   R[7] = oc*ny*nz + sn*nx;  R[8] = cs + oc*nz*nz;
    if (small) {
        float a  = 1.f  - t2/6.f;
        float bq = 0.5f - t2/24.f;
        R[0] = 1.f + bq*(x*x - t2);  R[1] = bq*x*y - a*z;        R[2] = bq*x*z + a*y;
        R[3] = bq*x*y + a*z;         R[4] = 1.f + bq*(y*y - t2); R[5] = bq*y*z - a*x;
        R[6] = bq*x*z - a*y;         R[7] = bq*y*z + a*x;        R[8] = 1.f + bq*(z*z - t2);
    }
}

// ---------------- fused prep: B' pack + JS fold + weight transpose ------------
__global__ void __launch_bounds__(256) k_prep(const float* __restrict__ pd,
                                              const float* __restrict__ sd,
                                              const float* __restrict__ Jreg,
                                              const float* __restrict__ mu,
                                              const float* __restrict__ w) {
    if (blockIdx.x < NBB) {
        int t = blockIdx.x*256 + threadIdx.x;
        if (t >= NPAD*56) return;
        int n = t / 56, q = t % 56;
        int kbase = q*8;
        union { unsigned short s[8]; uint4 v; } pk;
        #pragma unroll
        for (int i = 0; i < 8; i++) {
            int k = kbase + i;
            int seg = (k < KSEG) ? 0 : ((k < 2*KSEG) ? 1 : ((k < 3*KSEG) ? 2 : 3));
            int kr  = k - seg*KSEG;
            float f = 0.f;
            if (seg < 3 && n < NV) {
                f = (kr < 135) ? pd[n*135 + kr] : sd[n*10 + (kr - 135)];
            }
            pk.s[i] = (seg == 2) ? bf_lo(f) : bf_hi(f);
        }
        *(uint4*)(g_B2 + (size_t)n*KBIG + kbase) = pk.v;
    } else if (blockIdx.x < NBB + 66) {
        int wi = (blockIdx.x - NBB)*8 + (threadIdx.x >> 5);
        int lane = threadIdx.x & 31;
        if (wi >= NJ*33) return;
        int j = wi / 33, rem = wi % 33, c = rem / 11, k = rem % 11;
        float s = 0.f;
        for (int m = lane; m < MESH; m += 32) {
            float jr = Jreg[j*MESH + m];
            float x  = (k < 10) ? sd[(m*3+c)*10 + k] : mu[m*3+c];
            s = fmaf(jr, x, s);
        }
        #pragma unroll
        for (int off = 16; off; off >>= 1) s += __shfl_xor_sync(0xffffffffu, s, off);
        if (lane == 0) g_JS[j*33 + c*11 + k] = s;
    } else {
        int idx = (blockIdx.x - NBB - 66)*256 + threadIdx.x;
        if (idx >= NJ*800) return;
        int j = idx / 800, m = idx % 800;
        g_wT[idx] = (m < MESH) ? w[m*16 + j] : 0.f;
    }
}

// ---------------- per-batch kinematics + A' pack (fused, rot-folded) ----------
__global__ void __launch_bounds__(256) k_batch(const float* __restrict__ theta,
                                               const float* __restrict__ beta,
                                               const float* __restrict__ hc,
                                               const float* __restrict__ hm) {
    __shared__ float su[8][160];
    int warp = threadIdx.x >> 5;
    int lane = threadIdx.x & 31;
    int b = blockIdx.x*8 + warp;
    if (b >= NB) return;

    float px, py, pz;
    if (lane == 0) { px = 3.14159265358979323846f; py = 0.f; pz = 0.f; }
    else if (lane <= 15) {
        int i3 = (lane-1)*3;
        float s0 = hm[i3], s1 = hm[i3+1], s2 = hm[i3+2];
        const float* th = theta + b*48 + 3;
        #pragma unroll 5
        for (int k = 0; k < 45; k++) {
            float t = th[k];
            const float* h = hc + k*45 + i3;
            s0 = fmaf(t, h[0], s0);
            s1 = fmaf(t, h[1], s1);
            s2 = fmaf(t, h[2], s2);
        }
        px = s0; py = s1; pz = s2;
    } else {
        px = theta[b*48]; py = theta[b*48+1]; pz = theta[b*48+2];
    }

    float R[9];
    rodrigues9(px, py, pz, R);

    if (lane >= 1 && lane <= 15) {
        float* u = su[warp] + (lane-1)*9;
        #pragma unroll
        for (int e = 0; e < 9; e++)
            u[e] = R[e] - ((e==0||e==4||e==8) ? 1.f : 0.f);
    }
    if (lane < 10) su[warp][135 + lane] = beta[b*10 + lane];
    __syncwarp();

    // pack A' row
    {
        const float* u = su[warp];
        #pragma unroll
        for (int q = lane; q < 56; q += 32) {
            int kbase = q*8;
            union { unsigned short s[8]; uint4 v; } pk;
            #pragma unroll
            for (int i = 0; i < 8; i++) {
                int k = kbase + i;
                int seg = (k < KSEG) ? 0 : ((k < 2*KSEG) ? 1 : ((k < 3*KSEG) ? 2 : 3));
                int kr  = k - seg*KSEG;
                float f = (seg < 3) ? u[kr] : 0.f;
                pk.s[i] = (seg == 1) ? bf_lo(f) : bf_hi(f);
            }
            *(uint4*)(g_A2 + (size_t)b*KBIG + kbase) = pk.v;
        }
    }

    int jj = (lane < 16) ? lane : 15;
    float Jx, Jy, Jz;
    {
        const float* JS = g_JS + jj*33;
        float a0 = JS[10], a1 = JS[21], a2 = JS[32];
        #pragma unroll
        for (int k = 0; k < 10; k++) {
            float bb = beta[b*10+k];
            a0 = fmaf(bb, JS[k],    a0);
            a1 = fmaf(bb, JS[11+k], a1);
            a2 = fmaf(bb, JS[22+k], a2);
        }
        Jx = a0; Jy = a1; Jz = a2;
    }

    int pj = (jj == 0) ? 0 : ((jj % 3 == 1) ? 0 : jj - 1);
    float Jpx = __shfl_sync(0xffffffffu, Jx, pj);
    float Jpy = __shfl_sync(0xffffffffu, Jy, pj);
    float Jpz = __shfl_sync(0xffffffffu, Jz, pj);
    float tx = (jj == 0) ? Jx : Jx - Jpx;
    float ty = (jj == 0) ? Jy : Jy - Jpy;
    float tz = (jj == 0) ? Jz : Jz - Jpz;

    float G[12] = {R[0],R[1],R[2],tx, R[3],R[4],R[5],ty, R[6],R[7],R[8],tz};
    int lvl = (jj == 0) ? 0 : ((jj-1)%3 + 1);
    #pragma unroll
    for (int r = 1; r <= 3; r++) {
        float Gp[12];
        #pragma unroll
        for (int e = 0; e < 12; e++) Gp[e] = __shfl_sync(0xffffffffu, G[e], pj);
        if (lvl == r) {
            float N[12];
            #pragma unroll
            for (int rr = 0; rr < 3; rr++) {
                #pragma unroll
                for (int cc = 0; cc < 4; cc++) {
                    float s = Gp[rr*4+0]*G[0*4+cc] + Gp[rr*4+1]*G[1*4+cc] + Gp[rr*4+2]*G[2*4+cc];
                    if (cc == 3) s += Gp[rr*4+3];
                    N[rr*4+cc] = s;
                }
            }
            #pragma unroll
            for (int e = 0; e < 12; e++) G[e] = N[e];
        }
    }

    // broadcast the global rotation (lane 16's R)
    float Rg[9];
    #pragma unroll
    for (int e = 0; e < 9; e++) Rg[e] = __shfl_sync(0xffffffffu, R[e], 16);

    if (lane < 16) {
        g_Jg[b*48 + jj*3 + 0] = Rg[0]*G[3] + Rg[1]*G[7] + Rg[2]*G[11];
        g_Jg[b*48 + jj*3 + 1] = Rg[3]*G[3] + Rg[4]*G[7] + Rg[5]*G[11];
        g_Jg[b*48 + jj*3 + 2] = Rg[6]*G[3] + Rg[7]*G[7] + Rg[8]*G[11];
        float M[12];
        #pragma unroll
        for (int rr = 0; rr < 3; rr++) {
            float cr = G[rr*4+0]*Jx + G[rr*4+1]*Jy + G[rr*4+2]*Jz;
            M[rr*4+0] = G[rr*4+0];
            M[rr*4+1] = G[rr*4+1];
            M[rr*4+2] = G[rr*4+2];
            M[rr*4+3] = G[rr*4+3] - cr;
        }
        float* Mo = g_M + b*192 + jj*12;
        #pragma unroll
        for (int rr = 0; rr < 3; rr++)
            #pragma unroll
            for (int cc = 0; cc < 4; cc++)
                Mo[rr*4+cc] = Rg[rr*3+0]*M[0*4+cc] + Rg[rr*3+1]*M[1*4+cc] + Rg[rr*3+2]*M[2*4+cc];
    }
}

// ---------------- mma.sync GEMM (3-stage pipeline, 2 CTA/SM) ------------------
#define STAGE_BYTES 32768

__global__ void __launch_bounds__(256, 2) k_mma2(const float* __restrict__ mu) {
    extern __shared__ char smem[];
    uint32_t sb = smem_u32(smem);
    int tid = threadIdx.x, wid = tid >> 5, lane = tid & 31;
    int bx = blockIdx.x, by = blockIdx.y;

    const __nv_bfloat16* Ag = g_A2 + (size_t)by*128*KBIG;
    const __nv_bfloat16* Bg = g_B2 + (size_t)bx*128*KBIG;

    int m0 = (wid >> 1)*32;
    int n0 = (wid & 1)*64;

    float acc[2][8][4];
    #pragma unroll
    for (int i = 0; i < 2; i++)
        #pragma unroll
        for (int j = 0; j < 8; j++)
            #pragma unroll
            for (int e = 0; e < 4; e++) acc[i][j][e] = 0.f;

    auto load_stage = [&](int kc, int s) {
        uint32_t dA = sb + s*STAGE_BYTES;
        uint32_t dB = dA + 16384;
        #pragma unroll
        for (int i = 0; i < 4; i++) {
            int idx = i*256 + tid;
            int row = idx >> 3, ch = idx & 7;
            int sw  = ch ^ (row & 7);
            CP_ASYNC16(dA + row*128 + sw*16,
                       (const char*)__cvta_generic_to_global(Ag + (size_t)row*KBIG + kc*KCH + ch*8));
            CP_ASYNC16(dB + row*128 + sw*16,
                       (const char*)__cvta_generic_to_global(Bg + (size_t)row*KBIG + kc*KCH + ch*8));
        }
        CP_COMMIT();
    };

    load_stage(0, 0);
    load_stage(1, 1);
    load_stage(2, 2);

    #pragma unroll
    for (int kc = 0; kc < NCHUNK; kc++) {
        if (kc <= NCHUNK - 3)      { CP_WAIT(2); }
        else if (kc == NCHUNK - 2) { CP_WAIT(1); }
        else                       { CP_WAIT(0); }
        __syncthreads();
        uint32_t A0 = sb + (kc % 3)*STAGE_BYTES;
        uint32_t B0 = A0 + 16384;
        #pragma unroll
        for (int kk = 0; kk < 4; kk++) {
            uint32_t a[2][4];
            #pragma unroll
            for (int mf = 0; mf < 2; mf++) {
                int row = m0 + mf*16 + (lane & 15);
                int ch  = kk*2 + (lane >> 4);
                LDSM_X4(a[mf], A0 + row*128 + (ch ^ (row & 7))*16);
            }
            uint32_t bfr[4][4];
            #pragma unroll
            for (int nf2 = 0; nf2 < 4; nf2++) {
                int rn = n0 + nf2*16 + ((lane >> 4) & 1)*8 + (lane & 7);
                int ch = kk*2 + ((lane >> 3) & 1);
                LDSM_X4(bfr[nf2], B0 + rn*128 + (ch ^ (rn & 7))*16);
            }
            #pragma unroll
            for (int mf = 0; mf < 2; mf++)
                #pragma unroll
                for (int nf2 = 0; nf2 < 4; nf2++) {
                    MMA16816(acc[mf][2*nf2],   a[mf], bfr[nf2][0], bfr[nf2][1]);
                    MMA16816(acc[mf][2*nf2+1], a[mf], bfr[nf2][2], bfr[nf2][3]);
                }
        }
        __syncthreads();
        if (kc + 3 < NCHUNK) load_stage(kc + 3, kc % 3);
    }

    int qr = lane >> 2, qc = (lane & 3)*2;
    #pragma unroll
    for (int mf = 0; mf < 2; mf++) {
        int r0 = by*128 + m0 + mf*16 + qr;
        #pragma unroll
        for (int nf = 0; nf < 8; nf++) {
            int c = bx*128 + n0 + nf*8 + qc;
            float mv0 = (c   < NV) ? mu[c]   : 0.f;
            float mv1 = (c+1 < NV) ? mu[c+1] : 0.f;
            float2 v0 = make_float2(acc[mf][nf][0] + mv0, acc[mf][nf][1] + mv1);
            float2 v1 = make_float2(acc[mf][nf][2] + mv0, acc[mf][nf][3] + mv1);
            *(float2*)(g_vp + (size_t)r0*NPAD + c)       = v0;
            *(float2*)(g_vp + (size_t)(r0+8)*NPAD + c)   = v1;
        }
    }
}

// ---------------- skinning v6: v4 structure + smem weights + 3 CTAs/SM --------
#define BG 8
#define SKT 288
#define SK_SMEM (4*192*8 + NJ*800*4)   // 57344 B

__global__ void __launch_bounds__(SKT, 3) k_skin(float* __restrict__ out) {
    extern __shared__ char dsm[];
    ull*   sA = (ull*)dsm;               // [4][192]
    float* sW = (float*)(dsm + 4*192*8); // [16][800]
    int by = blockIdx.x;
    int tx = threadIdx.x;

    for (int i = tx; i < 4*192; i += SKT) {
        int pr = i / 192, e = i % 192;
        int b0 = by*BG + pr*2;
        sA[i] = pk2(g_M[(size_t)b0*192 + e], g_M[(size_t)(b0+1)*192 + e]);
    }
    {
        const float4* src = (const float4*)g_wT;
        float4* dst = (float4*)sW;
        for (int i = tx; i < NJ*200; i += SKT) dst[i] = src[i];
    }
    __syncthreads();

    int  mv[3];
    bool ok[3];
    int  tp[3];
    #pragma unroll
    for (int v = 0; v < 3; v++) {
        int m = v*SKT + tx;
        mv[v] = m;
        ok[v] = (m < MESH);
        tp[v] = -1;
        if (m == 333) tp[v] = 0; else if (m == 444) tp[v] = 1;
        else if (m == 672) tp[v] = 2; else if (m == 555) tp[v] = 3;
        else if (m == 745) tp[v] = 4;
    }

    #pragma unroll 1
    for (int pr = 0; pr < 4; pr++) {
        int b0 = by*BG + pr*2;

        ull pv[3][3];
        #pragma unroll
        for (int v = 0; v < 3; v++) {
            if (ok[v]) {
                const float* va = g_vp + (size_t)b0*NPAD + mv[v]*3;
                const float* vb = g_vp + (size_t)(b0+1)*NPAD + mv[v]*3;
                pv[v][0] = pk2(va[0], vb[0]);
                pv[v][1] = pk2(va[1], vb[1]);
                pv[v][2] = pk2(va[2], vb[2]);
            }
        }

        ull aX[3], aY[3], aZ[3];
        #pragma unroll
        for (int v = 0; v < 3; v++) { aX[v] = 0; aY[v] = 0; aZ[v] = 0; }

        const ull* sMp = sA + pr*192;
        #pragma unroll
        for (int j = 0; j < 16; j++) {
            ull A0 = sMp[j*12+0], A1 = sMp[j*12+1], A2  = sMp[j*12+2],  A3  = sMp[j*12+3];
            ull A4 = sMp[j*12+4], A5 = sMp[j*12+5], A6  = sMp[j*12+6],  A7  = sMp[j*12+7];
            ull A8 = sMp[j*12+8], A9 = sMp[j*12+9], A10 = sMp[j*12+10], A11 = sMp[j*12+11];
            const float* wrow = sW + j*800;
            #pragma unroll
            for (int v = 0; v < 3; v++) {
                if (!ok[v]) continue;
                float ws = wrow[mv[v]];
                ull wj = pk2(ws, ws);
                ull r0 = A3, r1 = A7, r2 = A11;
                FFMA2(r0, A2,  pv[v][2], r0); FFMA2(r0, A1, pv[v][1], r0); FFMA2(r0, A0, pv[v][0], r0);
                FFMA2(r1, A6,  pv[v][2], r1); FFMA2(r1, A5, pv[v][1], r1); FFMA2(r1, A4, pv[v][0], r1);
                FFMA2(r2, A10, pv[v][2], r2); FFMA2(r2, A9, pv[v][1], r2); FFMA2(r2, A8, pv[v][0], r2);
                FFMA2(aX[v], wj, r0, aX[v]);
                FFMA2(aY[v], wj, r1, aY[v]);
                FFMA2(aZ[v], wj, r2, aZ[v]);
            }
        }

        #pragma unroll
        for (int v = 0; v < 3; v++) {
            if (!ok[v]) continue;
            float xa, xb, ya, yb, za, zb;
            upk2(aX[v], xa, xb); upk2(aY[v], ya, yb); upk2(aZ[v], za, zb);
            if (tp[v] >= 0) {
                int t = tp[v];
                g_tips[b0*15 + t*3 + 0] = xa;  g_tips[(b0+1)*15 + t*3 + 0] = xb;
                g_tips[b0*15 + t*3 + 1] = ya;  g_tips[(b0+1)*15 + t*3 + 1] = yb;
                g_tips[b0*15 + t*3 + 2] = za;  g_tips[(b0+1)*15 + t*3 + 2] = zb;
            }
            float* oa = out + (size_t)(b0*MESH + mv[v])*3;
            float* ob = out + (size_t)((b0+1)*MESH + mv[v])*3;
            oa[0] = xa; oa[1] = ya; oa[2] = za;
            ob[0] = xb; ob[1] = yb; ob[2] = zb;
        }
    }
}

// ---------------- joints (21): pure gather + 2D projection --------------------
__global__ void k_joints(const float* __restrict__ cam, float* __restrict__ out) {
    int idx = blockIdx.x*256 + threadIdx.x;
    if (idx >= NB*21) return;
    int b = idx / 21, s = idx % 21;
    int src = c_src21[s];
    float x, y, z;
    if (src < 16) {
        x = g_Jg[b*48 + src*3 + 0];
        y = g_Jg[b*48 + src*3 + 1];
        z = g_Jg[b*48 + src*3 + 2];
    } else {
        int t = src - 16;
        x = g_tips[b*15 + t*3 + 0];
        y = g_tips[b*15 + t*3 + 1];
        z = g_tips[b*15 + t*3 + 2];
    }
    out[OUT_J_OFF + idx*3 + 0] = x;
    out[OUT_J_OFF + idx*3 + 1] = y;
    out[OUT_J_OFF + idx*3 + 2] = z;
    float c0 = cam[b*3], c1 = cam[b*3+1], c2 = cam[b*3+2];
    out[OUT_2D_OFF + idx*2 + 0] = fmaf(c0, x, c1);
    out[OUT_2D_OFF + idx*2 + 1] = fmaf(c0, y, c2);
}

// ---------------- launch ----------------
extern "C" void kernel_launch(void* const* d_in, const int* in_sizes, int n_in,
                              void* d_out, int out_size) {
    const float* theta     = (const float*)d_in[0];
    const float* beta      = (const float*)d_in[1];
    const float* cam       = (const float*)d_in[2];
    const float* mesh_mu   = (const float*)d_in[3];
    const float* shapedirs = (const float*)d_in[4];
    const float* posedirs  = (const float*)d_in[5];
    const float* Jreg      = (const float*)d_in[6];
    const float* weights   = (const float*)d_in[7];
    const float* hc        = (const float*)d_in[8];
    const float* hm        = (const float*)d_in[9];
    float* out = (float*)d_out;

    cudaFuncSetAttribute(k_mma2, cudaFuncAttributeMaxDynamicSharedMemorySize, 3*STAGE_BYTES);
    cudaFuncSetAttribute(k_skin, cudaFuncAttributeMaxDynamicSharedMemorySize, SK_SMEM);

    k_prep<<<NBB + 66 + NWB, 256>>>(posedirs, shapedirs, Jreg, mesh_mu, weights);
    k_batch<<<NB/8, 256>>>(theta, beta, hc, hm);
    dim3 gm(NPAD/128, NB/128);
    k_mma2<<<gm, 256, 3*STAGE_BYTES>>>(mesh_mu);
    k_skin<<<NB/BG, SKT, SK_SMEM>>>(out);
    k_joints<<<(NB*21 + 255)/256, 256>>>(cam, out);
}